// round 17
// baseline (speedup 1.0000x reference)
#include <cuda_runtime.h>
#include <math.h>
#include <stdint.h>

#define B_  16
#define L_  1024
#define H_  8
#define E_  64
#define D_  512
#define LF  513
#define NF  1024
#define QN  (B_*L_*D_)
#define WN  (1024*512*3)

// ---------------- scratch (device globals; no allocations) ----------------
__device__ float  g_qr[QN];                  // tf32-rounded q
__device__ float  g_Wr[WN];                  // tf32-rounded W
__device__ float  g_q2[B_*L_*D_];            // conv+GLU output, [B,L,D]
__device__ float2 g_qf[B_*H_*E_*LF];
__device__ float2 g_kf[B_*H_*E_*LF];
__device__ float2 g_vf[B_*H_*E_*LF];
__device__ float2 g_of[B_*H_*E_*LF];

// ======================= helpers ==========================================
__device__ __forceinline__ uint32_t smem_u32(const void* p) {
    uint32_t a;
    asm("{ .reg .u64 t; cvta.to.shared.u64 t, %1; cvt.u32.u64 %0, t; }"
        : "=r"(a) : "l"(p));
    return a;
}
__device__ __forceinline__ float tf32r(float x) {   // round-to-nearest tf32
    float y; asm("cvt.rna.tf32.f32 %0, %1;" : "=f"(y) : "f"(x)); return y;
}
__device__ __forceinline__ float sqrt_ap(float x) {
    float y; asm("sqrt.approx.f32 %0, %1;" : "=f"(y) : "f"(x)); return y;
}

#define MMA_TF32(c, a, b0v, b1v) \
    asm volatile("mma.sync.aligned.m16n8k8.row.col.f32.tf32.tf32.f32 " \
        "{%0,%1,%2,%3}, {%4,%5,%6,%7}, {%8,%9}, {%0,%1,%2,%3};" \
        : "+f"((c)[0]), "+f"((c)[1]), "+f"((c)[2]), "+f"((c)[3]) \
        : "r"((a)[0]), "r"((a)[1]), "r"((a)[2]), "r"((a)[3]), \
          "r"(b0v), "r"(b1v))

// ======================= 0) pre-round q and W to tf32 ======================
__global__ __launch_bounds__(256) void preround_kernel(
    const float* __restrict__ q, const float* __restrict__ W)
{
    int i0 = blockIdx.x * blockDim.x + threadIdx.x;
    int stride = gridDim.x * blockDim.x;
    for (int i = i0; i < QN; i += stride) g_qr[i] = tf32r(q[i]);
    for (int i = i0; i < WN; i += stride) g_Wr[i] = tf32r(W[i]);
}

// ======================= 1) Conv1d+GLU via mma.sync tf32 ==================
// (R6 version — verified passing; unchanged this round)
#define CONV_SMEM (18432*4)

__global__ __launch_bounds__(256) void conv_mma_kernel(
    const float* __restrict__ bias, float* __restrict__ q2out)
{
    extern __shared__ float smf[];
    const int tid  = threadIdx.x;
    const int wid  = tid >> 5;
    const int lane = tid & 31;
    const int gid  = lane >> 2;          // 0..7
    const int tg   = lane & 3;           // 0..3
    const int mw   = wid & 3;            // 4 m-sections of 32
    const int nw   = wid >> 2;           // 2 n-sections of 64
    const int mtile = blockIdx.x;        // 0..127
    const int obase = blockIdx.y * 64;   // 0..448
    const int b  = mtile >> 3;
    const int l0 = (mtile & 7) * 128;
    const uint32_t sb = smem_u32(smf);
    const float* qb = g_qr + (size_t)b * L_ * D_;

    float C[2][8][4];
    #pragma unroll
    for (int mf = 0; mf < 2; ++mf)
        #pragma unroll
        for (int j = 0; j < 8; ++j)
            #pragma unroll
            for (int u = 0; u < 4; ++u) C[mf][j][u] = 0.f;

    auto issue = [&](int c, int bf) {
        #pragma unroll
        for (int j = 0; j < 16; ++j) {
            int linear = j * 256 + tid;
            int m  = linear & 127;
            int kk = linear >> 7;
            int k  = c * 32 + kk;
            int i  = k / 3;
            int t  = k - 3 * i;
            int lt = l0 + m + t - 1;
            int ltc = lt < 0 ? 0 : (lt > L_-1 ? L_-1 : lt);
            const float* src = qb + (size_t)ltc * D_ + i;
            int ss = (lt >= 0 && lt < L_) ? 4 : 0;
            uint32_t sa = sb + (uint32_t)(bf*4608 + m*36 + kk) * 4;
            asm volatile("cp.async.ca.shared.global [%0], [%1], 4, %2;"
                         :: "r"(sa), "l"(src), "r"(ss));
        }
        #pragma unroll
        for (int j = 0; j < 4; ++j) {
            int linear = j * 256 + tid;
            int n   = linear >> 3;
            int kk4 = linear & 7;
            int grow = ((n & 1) ? 512 : 0) + obase + (n >> 1);
            const float* src = g_Wr + (size_t)grow * 1536 + c * 32 + kk4 * 4;
            uint32_t sa = sb + (uint32_t)(9216 + bf*4608 + n*36 + kk4*4) * 4;
            asm volatile("cp.async.ca.shared.global [%0], [%1], 16, 16;"
                         :: "r"(sa), "l"(src));
        }
        asm volatile("cp.async.commit_group;");
    };

    issue(0, 0);
    for (int c = 0; c < 48; ++c) {
        const int bf = c & 1;
        if (c + 1 < 48) {
            issue(c + 1, bf ^ 1);
            asm volatile("cp.async.wait_group 1;");
        } else {
            asm volatile("cp.async.wait_group 0;");
        }
        __syncthreads();

        const float* Abase = smf + bf*4608;
        const float* Bbase = smf + 9216 + bf*4608;
        #pragma unroll
        for (int k8 = 0; k8 < 4; ++k8) {
            uint32_t af[2][4];
            #pragma unroll
            for (int mf = 0; mf < 2; ++mf) {
                const float* Ap = Abase + (mw*32 + mf*16 + gid)*36 + k8*8;
                af[mf][0] = __float_as_uint(Ap[tg]);
                af[mf][1] = __float_as_uint(Ap[8*36 + tg]);
                af[mf][2] = __float_as_uint(Ap[tg + 4]);
                af[mf][3] = __float_as_uint(Ap[8*36 + tg + 4]);
            }
            #pragma unroll
            for (int j = 0; j < 8; ++j) {
                const float* Bp = Bbase + (nw*64 + j*8 + gid)*36 + k8*8;
                uint32_t b0 = __float_as_uint(Bp[tg]);
                uint32_t b1 = __float_as_uint(Bp[tg + 4]);
                MMA_TF32(C[0][j], af[0], b0, b1);
                MMA_TF32(C[1][j], af[1], b0, b1);
            }
        }
        __syncthreads();
    }

    #pragma unroll
    for (int mf = 0; mf < 2; ++mf) {
        int r0 = mtile*128 + mw*32 + mf*16 + gid;
        #pragma unroll
        for (int j = 0; j < 8; ++j) {
            int och = obase + nw*32 + j*4 + tg;
            float ba = bias[och], bg = bias[512 + och];
            float a0 = C[mf][j][0] + ba, g0 = C[mf][j][1] + bg;
            float a1 = C[mf][j][2] + ba, g1 = C[mf][j][3] + bg;
            q2out[(size_t)r0*D_ + och]       = a0 / (1.f + __expf(-g0));
            q2out[(size_t)(r0+8)*D_ + och]   = a1 / (1.f + __expf(-g1));
        }
    }
}

// ======================= radix-2 FFT (1024-pt, smem) =======================
__device__ __forceinline__ void fft1024_smem(float* re, float* im,
                                             const float2* tw, int tid)
{
    for (int len = 2; len <= NF; len <<= 1) {
        int half  = len >> 1;
        int tstep = NF / len;
        for (int bi = tid; bi < NF/2; bi += 256) {
            int grp = bi / half;
            int pos = bi - grp*half;
            int i0 = grp*len + pos;
            int i1 = i0 + half;
            float2 w = tw[pos * tstep];
            float vr = re[i1], vi = im[i1];
            float tr = w.x*vr - w.y*vi;
            float ti = w.x*vi + w.y*vr;
            float ur = re[i0], ui = im[i0];
            re[i0] = ur + tr; im[i0] = ui + ti;
            re[i1] = ur - tr; im[i1] = ui - ti;
        }
        __syncthreads();
    }
}

// ============== 2a) rfft of k & v packed: z = k + i*v ======================
__global__ __launch_bounds__(256) void rfft_kv_kernel(
    const float* __restrict__ kin, const float* __restrict__ vin)
{
    __shared__ float  sre[NF], sim[NF];
    __shared__ float2 tw[NF/2];
    const int tid = threadIdx.x;
    const int bc  = blockIdx.x;              // b*512 + c
    for (int j = tid; j < NF/2; j += 256) {
        float s, c;
        sincosf(-6.283185307179586f * (float)j / (float)NF, &s, &c);
        tw[j] = make_float2(c, s);
    }
    const float* kp = kin + (size_t)(bc >> 9)*L_*D_ + (bc & 511);
    const float* vp = vin + (size_t)(bc >> 9)*L_*D_ + (bc & 511);
    for (int n = tid; n < NF; n += 256) {
        int r = __brev(n) >> 22;
        sre[r] = kp[(size_t)n * D_];
        sim[r] = vp[(size_t)n * D_];
    }
    __syncthreads();
    fft1024_smem(sre, sim, tw, tid);

    const float sc_ = 0.03125f;
    float2* kf = g_kf + (size_t)bc * LF;
    float2* vf = g_vf + (size_t)bc * LF;
    for (int x = tid; x < LF; x += 256) {
        int xm = (NF - x) & (NF - 1);
        float Pr = sre[x], Pi = sim[x], Qr = sre[xm], Qi = sim[xm];
        kf[x] = make_float2(0.5f*(Pr + Qr)*sc_, 0.5f*(Pi - Qi)*sc_);
        vf[x] = make_float2(0.5f*(Pi + Qi)*sc_, 0.5f*(Qr - Pr)*sc_);
    }
}

// ============== 2b) rfft of q2 packed channel pairs ========================
__global__ __launch_bounds__(256) void rfft_q_kernel()
{
    __shared__ float  sre[NF], sim[NF];
    __shared__ float2 tw[NF/2];
    const int tid = threadIdx.x;
    const int bc2 = blockIdx.x;              // b*256 + pair
    const int b   = bc2 >> 8;
    const int c0  = (bc2 & 255) * 2;
    for (int j = tid; j < NF/2; j += 256) {
        float s, c;
        sincosf(-6.283185307179586f * (float)j / (float)NF, &s, &c);
        tw[j] = make_float2(c, s);
    }
    const float* q0 = g_q2 + (size_t)b*L_*D_ + c0;
    for (int n = tid; n < NF; n += 256) {
        int r = __brev(n) >> 22;
        sre[r] = q0[(size_t)n * D_];
        sim[r] = q0[(size_t)n * D_ + 1];
    }
    __syncthreads();
    fft1024_smem(sre, sim, tw, tid);

    const float sc_ = 0.03125f;
    float2* f0 = g_qf + (size_t)(b*512 + c0) * LF;
    float2* f1 = f0 + LF;
    for (int x = tid; x < LF; x += 256) {
        int xm = (NF - x) & (NF - 1);
        float Pr = sre[x], Pi = sim[x], Qr = sre[xm], Qi = sim[xm];
        f0[x] = make_float2(0.5f*(Pr + Qr)*sc_, 0.5f*(Pi - Qi)*sc_);
        f1[x] = make_float2(0.5f*(Pi + Qi)*sc_, 0.5f*(Qr - Pr)*sc_);
    }
}

// ======================= 3) attention via mma.sync tf32 ====================
// s = (qf^T conj(kf))/8;  g = 1 + sigmoid(|s|);
// of = (sum_y s*g*vf) / max(sum_y |s|*g, 1e-12).
// tf32 MMA operands rounded with cvt.rna (no truncation bias); imaginary
// negation via register XOR (no extra smem arrays).
struct AttnSmem2 {
    float Qr[64][68], Qi[64][68];           // [x][e]
    float Kr[64][68], Ki[64][68];           // [y][e]
    float Vr[64][68], Vi[64][68];           // [e][y]
    float Ssr[64][68], Ssi[64][68];         // [x][y], gated
    float rsum[64];
    float rinv[64];
};

__global__ __launch_bounds__(256) void attn_mma_kernel()
{
    extern __shared__ char sraw[];
    AttnSmem2& sm = *reinterpret_cast<AttnSmem2*>(sraw);
    const int tid  = threadIdx.x;
    const int wid  = tid >> 5;
    const int lane = tid & 31;
    const int gid  = lane >> 2;
    const int tg   = lane & 3;
    const int mw   = wid & 3;      // x quarter (16 rows)
    const int nw   = wid >> 2;     // y/e half (32 cols)
    const int xbase = blockIdx.x * 64;
    const int bh    = blockIdx.y;
    const uint32_t SGN = 0x80000000u;

    const float2* qf = g_qf + (size_t)bh * E_ * LF;
    const float2* kf = g_kf + (size_t)bh * E_ * LF;
    const float2* vf = g_vf + (size_t)bh * E_ * LF;
    float2*       of = g_of + (size_t)bh * E_ * LF;

    if (tid < 64) sm.rsum[tid] = 0.f;

    for (int i = tid; i < 4096; i += 256) {
        int e = i >> 6, xx = i & 63;
        int x = xbase + xx;
        float2 v = make_float2(0.f, 0.f);
        if (x < LF) v = qf[(size_t)e*LF + x];
        sm.Qr[xx][e] = tf32r(v.x * 0.125f);
        sm.Qi[xx][e] = tf32r(v.y * 0.125f);
    }

    float ofr[4][4], ofi[4][4];
    #pragma unroll
    for (int j = 0; j < 4; ++j)
        #pragma unroll
        for (int u = 0; u < 4; ++u) { ofr[j][u] = 0.f; ofi[j][u] = 0.f; }
    float rs0 = 0.f, rs1 = 0.f;

    for (int yt = 0; yt < 9; ++yt) {
        const int ybase = yt * 64;
        __syncthreads();
        for (int i = tid; i < 4096; i += 256) {
            int e = i >> 6, yy = i & 63;
            int y = ybase + yy;
            float2 kv = make_float2(0.f, 0.f), vv = make_float2(0.f, 0.f);
            if (y < LF) { kv = kf[(size_t)e*LF + y]; vv = vf[(size_t)e*LF + y]; }
            sm.Kr[yy][e] = tf32r(kv.x); sm.Ki[yy][e] = tf32r(kv.y);
            sm.Vr[e][yy] = tf32r(vv.x); sm.Vi[e][yy] = tf32r(vv.y);
        }
        __syncthreads();

        // ---- phase 1: S = Q * conj(K)^T ----
        float Sr[4][4], Si[4][4];
        #pragma unroll
        for (int j = 0; j < 4; ++j)
            #pragma unroll
            for (int u = 0; u < 4; ++u) { Sr[j][u] = 0.f; Si[j][u] = 0.f; }

        #pragma unroll
        for (int k8 = 0; k8 < 8; ++k8) {
            uint32_t ar[4], ai[4];
            {
                const float* Qrp = &sm.Qr[mw*16 + gid][k8*8];
                const float* Qip = &sm.Qi[mw*16 + gid][k8*8];
                ar[0]=__float_as_uint(Qrp[tg]);      ar[1]=__float_as_uint(Qrp[8*68+tg]);
                ar[2]=__float_as_uint(Qrp[tg+4]);    ar[3]=__float_as_uint(Qrp[8*68+tg+4]);
                ai[0]=__float_as_uint(Qip[tg]);      ai[1]=__float_as_uint(Qip[8*68+tg]);
                ai[2]=__float_as_uint(Qip[tg+4]);    ai[3]=__float_as_uint(Qip[8*68+tg+4]);
            }
            #pragma unroll
            for (int j = 0; j < 4; ++j) {
                int nr = nw*32 + j*8 + gid;
                const float* Krp = &sm.Kr[nr][k8*8];
                const float* Kip = &sm.Ki[nr][k8*8];
                uint32_t kr0=__float_as_uint(Krp[tg]), kr1=__float_as_uint(Krp[tg+4]);
                uint32_t ki0=__float_as_uint(Kip[tg]), ki1=__float_as_uint(Kip[tg+4]);
                uint32_t kn0 = ki0 ^ SGN, kn1 = ki1 ^ SGN;
                MMA_TF32(Sr[j], ar, kr0, kr1);
                MMA_TF32(Sr[j], ai, ki0, ki1);
                MMA_TF32(Si[j], ai, kr0, kr1);
                MMA_TF32(Si[j], ar, kn0, kn1);
            }
        }

        // ---- gating: g = 1 + sigmoid(m); store tf32(S*g); rsum += m*g ----
        #pragma unroll
        for (int j = 0; j < 4; ++j) {
            #pragma unroll
            for (int h = 0; h < 2; ++h) {
                float re0 = Sr[j][h ? 2 : 0], im0 = Si[j][h ? 2 : 0];
                float re1 = Sr[j][h ? 3 : 1], im1 = Si[j][h ? 3 : 1];
                float m0 = sqrt_ap(fmaf(re0, re0, im0*im0));
                float m1 = sqrt_ap(fmaf(re1, re1, im1*im1));
                float g0 = 1.f + __fdividef(1.f, 1.f + __expf(-m0));
                float g1 = 1.f + __fdividef(1.f, 1.f + __expf(-m1));
                if (h) rs1 += fmaf(m0, g0, m1*g1); else rs0 += fmaf(m0, g0, m1*g1);
                int row = mw*16 + gid + h*8;
                int cb  = nw*32 + j*8 + 2*tg;
                *(float2*)&sm.Ssr[row][cb] = make_float2(tf32r(re0*g0), tf32r(re1*g1));
                *(float2*)&sm.Ssi[row][cb] = make_float2(tf32r(im0*g0), tf32r(im1*g1));
            }
        }
        __syncthreads();

        // ---- phase 2: OF += Sgated * V^T ----
        #pragma unroll
        for (int k8 = 0; k8 < 8; ++k8) {
            uint32_t asr[4], asi[4];
            {
                const float* Srp = &sm.Ssr[mw*16 + gid][k8*8];
                const float* Sip = &sm.Ssi[mw*16 + gid][k8*8];
                asr[0]=__float_as_uint(Srp[tg]);      asr[1]=__float_as_uint(Srp[8*68+tg]);
                asr[2]=__float_as_uint(Srp[tg+4]);    asr[3]=__float_as_uint(Srp[8*68+tg+4]);
                asi[0]=__float_as_uint(Sip[tg]);      asi[1]=__float_as_uint(Sip[8*68+tg]);
                asi[2]=__float_as_uint(Sip[tg+4]);    asi[3]=__float_as_uint(Sip[8*68+tg+4]);
            }
            #pragma unroll
            for (int j = 0; j < 4; ++j) {
                int nr = nw*32 + j*8 + gid;
                const float* Vrp = &sm.Vr[nr][k8*8];
                const float* Vip = &sm.Vi[nr][k8*8];
                uint32_t vr0=__float_as_uint(Vrp[tg]), vr1=__float_as_uint(Vrp[tg+4]);
                uint32_t vi0=__float_as_uint(Vip[tg]), vi1=__float_as_uint(Vip[tg+4]);
                uint32_t vn0 = vi0 ^ SGN, vn1 = vi1 ^ SGN;
                MMA_TF32(ofr[j], asr, vr0, vr1);
                MMA_TF32(ofr[j], asi, vn0, vn1);
                MMA_TF32(ofi[j], asr, vi0, vi1);
                MMA_TF32(ofi[j], asi, vr0, vr1);
            }
        }
    }

    // ---- rsum reduce: quad shfl + smem atomics ----
    rs0 += __shfl_xor_sync(0xFFFFFFFF, rs0, 1);
    rs0 += __shfl_xor_sync(0xFFFFFFFF, rs0, 2);
    rs1 += __shfl_xor_sync(0xFFFFFFFF, rs1, 1);
    rs1 += __shfl_xor_sync(0xFFFFFFFF, rs1, 2);
    if (tg == 0) {
        atomicAdd(&sm.rsum[mw*16 + gid],     rs0);
        atomicAdd(&sm.rsum[mw*16 + gid + 8], rs1);
    }
    __syncthreads();
    if (tid < 64) sm.rinv[tid] = 1.f / fmaxf(sm.rsum[tid], 1e-12f);
    __syncthreads();

    #pragma unroll
    for (int j = 0; j < 4; ++j) {
        #pragma unroll
        for (int u = 0; u < 4; ++u) {
            int row = mw*16 + gid + ((u >= 2) ? 8 : 0);
            int e   = nw*32 + j*8 + 2*tg + (u & 1);
            int x   = xbase + row;
            if (x < LF) {
                float ri = sm.rinv[row];
                of[(size_t)e*LF + x] = make_float2(ofr[j][u]*ri, ofi[j][u]*ri);
            }
        }
    }
}

// ======================= 4) irfft packed channel pairs =====================
__global__ __launch_bounds__(256) void irfft_kernel(float* __restrict__ out)
{
    __shared__ float  sre[NF], sim[NF];
    __shared__ float2 tw[NF/2];
    const int tid = threadIdx.x;
    const int bc2 = blockIdx.x;              // b*256 + pair
    const int b   = bc2 >> 8;
    const int c0  = (bc2 & 255) * 2;
    const float2* o0 = g_of + (size_t)(b*512 + c0) * LF;
    const float2* o1 = o0 + LF;

    for (int j = tid; j < NF/2; j += 256) {
        float s, c;
        sincosf(-6.283185307179586f * (float)j / (float)NF, &s, &c);
        tw[j] = make_float2(c, s);
    }
    for (int n = tid; n < NF; n += 256) {
        int k2 = (n <= 512) ? n : NF - n;
        float sg = (n <= 512) ? 1.f : -1.f;
        float zf = (k2 == 0 || k2 == 512) ? 0.f : 1.f;
        float2 A0 = o0[k2], A1 = o1[k2];
        A0.y *= zf; A1.y *= zf;
        float cre = A0.x - sg * A1.y;
        float cim = -sg * A0.y - A1.x;
        int r = __brev(n) >> 22;
        sre[r] = cre; sim[r] = cim;
    }
    __syncthreads();
    fft1024_smem(sre, sim, tw, tid);

    float* op = out + (size_t)b*L_*D_ + c0;
    for (int n = tid; n < NF; n += 256) {
        op[(size_t)n * D_]     =  sre[n] * 0.03125f;
        op[(size_t)n * D_ + 1] = -sim[n] * 0.03125f;
    }
}

// ============================== launcher ===================================
extern "C" void kernel_launch(void* const* d_in, const int* in_sizes, int n_in,
                              void* d_out, int out_size)
{
    const float* q    = (const float*)d_in[0];
    const float* k    = (const float*)d_in[1];
    const float* v    = (const float*)d_in[2];
    const float* W    = (const float*)d_in[3];
    const float* bias = (const float*)d_in[4];
    float* out = (float*)d_out;

    float* q2p;
    cudaGetSymbolAddress((void**)&q2p, g_q2);

    cudaFuncSetAttribute(conv_mma_kernel,
        cudaFuncAttributeMaxDynamicSharedMemorySize, CONV_SMEM);
    cudaFuncSetAttribute(attn_mma_kernel,
        cudaFuncAttributeMaxDynamicSharedMemorySize, (int)sizeof(AttnSmem2));

    preround_kernel<<<4096, 256>>>(q, W);
    conv_mma_kernel<<<dim3(128, 8), 256, CONV_SMEM>>>(bias, q2p);
    rfft_kv_kernel<<<B_*D_, 256>>>(k, v);
    rfft_q_kernel<<<B_*256, 256>>>();
    attn_mma_kernel<<<dim3(9, B_*H_), 256, sizeof(AttnSmem2)>>>();
    irfft_kernel<<<B_*256, 256>>>(out);
}